// round 1
// baseline (speedup 1.0000x reference)
#include <cuda_runtime.h>

// SparseBPNeuralNetwork — fused sparse BP decoder.
// N=648 vars, E=1944 edges, 324 checks (6 edges each, contiguous),
// each var has exactly 3 edges (one per layer l = e/648).
// 5 decoding iterations, outputs (out5, out4, out3, out2, out1) each [2048,648].

#define NV 648
#define NE 1944
#define BATCH 2048
#define NCHK 324
#define TOT (BATCH * NV)
#define CLAMPV 0.999999f

// ---- preprocessed graph/weight data (device globals; rewritten every launch) ----
__device__ int   g_var_of[NE];     // edge -> variable
__device__ int   g_eov[NV * 3];    // var,layer -> edge  (deterministic slot = layer)
__device__ int   g_j1[NE];         // extrinsic same-var partner 1
__device__ int   g_j2[NE];         // extrinsic same-var partner 2
__device__ float2 g_w[4][NE];      // per VN layer: (W[e][j1], W[e][j2])
__device__ float g_w9[NV][3];      // output weights per var (3 edges)

// ---------------- preprocessing ----------------
__global__ void prep1(const float* __restrict__ M_out) {
    int e = blockIdx.x * blockDim.x + threadIdx.x;
    if (e >= NE) return;
    int v = 0;
    for (int r = 0; r < NV; r++) {
        if (M_out[r * NE + e] != 0.0f) { v = r; break; }
    }
    g_var_of[e] = v;
    int l = e / NV;                 // each layer is a permutation of vars
    g_eov[v * 3 + l] = e;
}

__global__ void prep2(const float* __restrict__ W1, const float* __restrict__ W3,
                      const float* __restrict__ W5, const float* __restrict__ W7,
                      const float* __restrict__ W9) {
    int e = blockIdx.x * blockDim.x + threadIdx.x;
    if (e < NE) {
        int v = g_var_of[e];
        int l = e / NV;
        int j1 = g_eov[v * 3 + ((l + 1) % 3)];
        int j2 = g_eov[v * 3 + ((l + 2) % 3)];
        g_j1[e] = j1;
        g_j2[e] = j2;
        g_w[0][e] = make_float2(W1[(size_t)e * NE + j1], W1[(size_t)e * NE + j2]);
        g_w[1][e] = make_float2(W3[(size_t)e * NE + j1], W3[(size_t)e * NE + j2]);
        g_w[2][e] = make_float2(W5[(size_t)e * NE + j1], W5[(size_t)e * NE + j2]);
        g_w[3][e] = make_float2(W7[(size_t)e * NE + j1], W7[(size_t)e * NE + j2]);
    }
    if (e < NV) {
        int v = e;
        g_w9[v][0] = W9[(size_t)v * NE + g_eov[v * 3 + 0]];
        g_w9[v][1] = W9[(size_t)v * NE + g_eov[v * 3 + 1]];
        g_w9[v][2] = W9[(size_t)v * NE + g_eov[v * 3 + 2]];
    }
}

// ---------------- main fused kernel ----------------
__device__ __forceinline__ float atanh2f(float m) {
    // 2*atanh(m), matches reference's clip -> 2*arctanh
    return logf((1.0f + m) / (1.0f - m));
}
__device__ __forceinline__ float sigmoidf(float s) {
    return 1.0f / (1.0f + expf(-s));
}

__device__ __forceinline__ void cn_block(const float u[6], float tv[6]) {
    // extrinsic products within a 6-edge check via prefix/suffix
    float p1 = u[0] * u[1], p2 = p1 * u[2], p3 = p2 * u[3], p4 = p3 * u[4];
    float s4 = u[5] * u[4], s3 = s4 * u[3], s2 = s3 * u[2], s1 = s2 * u[1];
    float m[6];
    m[0] = s1;        m[1] = u[0] * s2; m[2] = p1 * s3;
    m[3] = p2 * s4;   m[4] = p3 * u[5]; m[5] = p4;
#pragma unroll
    for (int k = 0; k < 6; k++) {
        float mm = fminf(fmaxf(m[k], -CLAMPV), CLAMPV);
        tv[k] = atanh2f(mm);
    }
}

__global__ __launch_bounds__(NCHK)
void bp_main(const float* __restrict__ x, float* __restrict__ out) {
    __shared__ float s_llr[NV];
    __shared__ float s_t[2][NE];

    const int b   = blockIdx.x;
    const int tid = threadIdx.x;           // one check per thread, 324 threads

    // load channel LLRs for this batch row
    s_llr[tid]        = x[b * NV + tid];
    s_llr[tid + NCHK] = x[b * NV + tid + NCHK];

    const int ebase = tid * 6;
    int vo[6], j1[6], j2[6];
#pragma unroll
    for (int k = 0; k < 6; k++) {
        vo[k] = g_var_of[ebase + k];
        j1[k] = g_j1[ebase + k];
        j2[k] = g_j2[ebase + k];
    }
    // this thread also owns output vars v0 = tid, v1 = tid + 324
    const int v0 = tid, v1 = tid + NCHK;
    const int e0a = g_eov[v0 * 3 + 0], e0b = g_eov[v0 * 3 + 1], e0c = g_eov[v0 * 3 + 2];
    const int e1a = g_eov[v1 * 3 + 0], e1b = g_eov[v1 * 3 + 1], e1c = g_eov[v1 * 3 + 2];

    __syncthreads();

    float u[6], tv[6];

    // ---- iteration 1: CN update directly from channel LLRs ----
#pragma unroll
    for (int k = 0; k < 6; k++)
        u[k] = tanhf(0.5f * s_llr[vo[k]]);
    cn_block(u, tv);
#pragma unroll
    for (int k = 0; k < 6; k++) s_t[0][ebase + k] = tv[k];
    __syncthreads();

    // out1 (offset 4*TOT)
    {
        float sA = s_t[0][e0a] + s_t[0][e0b] + s_t[0][e0c] + s_llr[v0];
        float sB = s_t[0][e1a] + s_t[0][e1b] + s_t[0][e1c] + s_llr[v1];
        out[4 * TOT + b * NV + v0] = sigmoidf(sA);
        out[4 * TOT + b * NV + v1] = sigmoidf(sB);
    }

    // ---- iterations 2..5: VN update (2 weighted extrinsic msgs + llr) then CN ----
    int src = 0;
#pragma unroll
    for (int li = 0; li < 4; li++) {
        const int dst = src ^ 1;
#pragma unroll
        for (int k = 0; k < 6; k++) {
            float2 w = g_w[li][ebase + k];
            float vn = w.x * s_t[src][j1[k]] + w.y * s_t[src][j2[k]] + s_llr[vo[k]];
            u[k] = tanhf(0.5f * vn);
        }
        cn_block(u, tv);
        // writes go to dst (the buffer last read two barriers ago) -> safe w/o extra barrier
#pragma unroll
        for (int k = 0; k < 6; k++) s_t[dst][ebase + k] = tv[k];
        __syncthreads();

        if (li < 3) {
            // out2..out4 at offsets (3-li)*TOT
            float sA = s_t[dst][e0a] + s_t[dst][e0b] + s_t[dst][e0c] + s_llr[v0];
            float sB = s_t[dst][e1a] + s_t[dst][e1b] + s_t[dst][e1c] + s_llr[v1];
            int off = (3 - li) * TOT + b * NV;
            out[off + v0] = sigmoidf(sA);
            out[off + v1] = sigmoidf(sB);
        } else {
            // out5 at offset 0: W9-weighted sum + llr
            float sA = g_w9[v0][0] * s_t[dst][e0a] + g_w9[v0][1] * s_t[dst][e0b]
                     + g_w9[v0][2] * s_t[dst][e0c] + s_llr[v0];
            float sB = g_w9[v1][0] * s_t[dst][e1a] + g_w9[v1][1] * s_t[dst][e1b]
                     + g_w9[v1][2] * s_t[dst][e1c] + s_llr[v1];
            out[b * NV + v0] = sigmoidf(sA);
            out[b * NV + v1] = sigmoidf(sB);
        }
        src = dst;
    }
}

// ---------------- launch ----------------
extern "C" void kernel_launch(void* const* d_in, const int* in_sizes, int n_in,
                              void* d_out, int out_size) {
    // metadata order: x, M_first, M_cn, M_out, bias_matrix, W1, W3, W5, W7, W9, B0..B4
    const float* x     = (const float*)d_in[0];
    const float* M_out = (const float*)d_in[3];
    const float* W1    = (const float*)d_in[5];
    const float* W3    = (const float*)d_in[6];
    const float* W5    = (const float*)d_in[7];
    const float* W7    = (const float*)d_in[8];
    const float* W9    = (const float*)d_in[9];

    prep1<<<(NE + 255) / 256, 256>>>(M_out);
    prep2<<<(NE + 255) / 256, 256>>>(W1, W3, W5, W7, W9);
    bp_main<<<BATCH, NCHK>>>(x, (float*)d_out);
}

// round 2
// speedup vs baseline: 2.8739x; 2.8739x over previous
#include <cuda_runtime.h>

// SparseBPNeuralNetwork — fused sparse BP decoder, round 2.
// Changes vs round 1:
//  * prep1: data-parallel float4 scan of M_out (was per-edge serial search).
//  * bp_main: fast MUFU transcendentals (__expf/__logf/__fdividef).

#define NV 648
#define NE 1944
#define BATCH 2048
#define NCHK 324
#define TOT (BATCH * NV)
#define CLAMPV 0.999999f

// ---- preprocessed graph/weight data (device globals; rewritten every launch) ----
__device__ int    g_var_of[NE];     // edge -> variable
__device__ int    g_eov[NV * 3];    // var,layer -> edge  (slot = layer = e/NV)
__device__ int    g_j1[NE];         // extrinsic same-var partner 1
__device__ int    g_j2[NE];         // extrinsic same-var partner 2
__device__ float2 g_w[4][NE];       // per VN layer: (W[e][j1], W[e][j2])
__device__ float  g_w9[NV][3];      // output weights per var (3 edges)

// ---------------- preprocessing ----------------
// Full coalesced scan of M_out [NV, NE]: each nonzero (v,e) is unique, so the
// scatter stores are race-free. float4 since NE % 4 == 0.
__global__ void prep1(const float4* __restrict__ M_out4) {
    int idx = blockIdx.x * blockDim.x + threadIdx.x;     // over NV*NE/4
    if (idx >= NV * NE / 4) return;
    float4 val = M_out4[idx];
    if (val.x == 0.0f && val.y == 0.0f && val.z == 0.0f && val.w == 0.0f) return;
    int lin = idx * 4;
    int v = lin / NE;
    int e = lin - v * NE;
    float vv[4] = {val.x, val.y, val.z, val.w};
#pragma unroll
    for (int k = 0; k < 4; k++) {
        if (vv[k] != 0.0f) {
            int ek = e + k;
            g_var_of[ek] = v;
            g_eov[v * 3 + ek / NV] = ek;
        }
    }
}

__global__ void prep2(const float* __restrict__ W1, const float* __restrict__ W3,
                      const float* __restrict__ W5, const float* __restrict__ W7,
                      const float* __restrict__ W9) {
    int e = blockIdx.x * blockDim.x + threadIdx.x;
    if (e < NE) {
        int v = g_var_of[e];
        int l = e / NV;
        int j1 = g_eov[v * 3 + ((l + 1) % 3)];
        int j2 = g_eov[v * 3 + ((l + 2) % 3)];
        g_j1[e] = j1;
        g_j2[e] = j2;
        g_w[0][e] = make_float2(W1[(size_t)e * NE + j1], W1[(size_t)e * NE + j2]);
        g_w[1][e] = make_float2(W3[(size_t)e * NE + j1], W3[(size_t)e * NE + j2]);
        g_w[2][e] = make_float2(W5[(size_t)e * NE + j1], W5[(size_t)e * NE + j2]);
        g_w[3][e] = make_float2(W7[(size_t)e * NE + j1], W7[(size_t)e * NE + j2]);
    }
    if (e < NV) {
        int v = e;
        g_w9[v][0] = W9[(size_t)v * NE + g_eov[v * 3 + 0]];
        g_w9[v][1] = W9[(size_t)v * NE + g_eov[v * 3 + 1]];
        g_w9[v][2] = W9[(size_t)v * NE + g_eov[v * 3 + 2]];
    }
}

// ---------------- fast math ----------------
__device__ __forceinline__ float ftanh_half(float a) {
    // tanh(0.5*a) = (e^a - 1) / (e^a + 1); __expf of clamped arg avoids inf/inf
    float e = __expf(fminf(a, 80.0f));
    return __fdividef(e - 1.0f, e + 1.0f);
}
__device__ __forceinline__ float atanh2f(float m) {
    // 2*atanh(m) = log((1+m)/(1-m)); |m| <= 0.999999 so ratio in [1e-6, 2e6]
    return __logf(__fdividef(1.0f + m, 1.0f - m));
}
__device__ __forceinline__ float sigmoidf(float s) {
    return __fdividef(1.0f, 1.0f + __expf(-s));   // exp overflow -> inf -> 0, correct limit
}

__device__ __forceinline__ void cn_block(const float u[6], float tv[6]) {
    // extrinsic products within a 6-edge check via prefix/suffix
    float p1 = u[0] * u[1], p2 = p1 * u[2], p3 = p2 * u[3], p4 = p3 * u[4];
    float s4 = u[5] * u[4], s3 = s4 * u[3], s2 = s3 * u[2], s1 = s2 * u[1];
    float m[6];
    m[0] = s1;        m[1] = u[0] * s2; m[2] = p1 * s3;
    m[3] = p2 * s4;   m[4] = p3 * u[5]; m[5] = p4;
#pragma unroll
    for (int k = 0; k < 6; k++) {
        float mm = fminf(fmaxf(m[k], -CLAMPV), CLAMPV);
        tv[k] = atanh2f(mm);
    }
}

__global__ __launch_bounds__(NCHK)
void bp_main(const float* __restrict__ x, float* __restrict__ out) {
    __shared__ float s_llr[NV];
    __shared__ float s_t[2][NE];

    const int b   = blockIdx.x;
    const int tid = threadIdx.x;           // one check per thread, 324 threads

    s_llr[tid]        = x[b * NV + tid];
    s_llr[tid + NCHK] = x[b * NV + tid + NCHK];

    const int ebase = tid * 6;
    int vo[6], j1[6], j2[6];
#pragma unroll
    for (int k = 0; k < 6; k++) {
        vo[k] = g_var_of[ebase + k];
        j1[k] = g_j1[ebase + k];
        j2[k] = g_j2[ebase + k];
    }
    const int v0 = tid, v1 = tid + NCHK;
    const int e0a = g_eov[v0 * 3 + 0], e0b = g_eov[v0 * 3 + 1], e0c = g_eov[v0 * 3 + 2];
    const int e1a = g_eov[v1 * 3 + 0], e1b = g_eov[v1 * 3 + 1], e1c = g_eov[v1 * 3 + 2];

    __syncthreads();

    float u[6], tv[6];

    // ---- iteration 1: CN update directly from channel LLRs ----
#pragma unroll
    for (int k = 0; k < 6; k++)
        u[k] = ftanh_half(s_llr[vo[k]]);
    cn_block(u, tv);
#pragma unroll
    for (int k = 0; k < 6; k++) s_t[0][ebase + k] = tv[k];
    __syncthreads();

    // out1 (offset 4*TOT)
    {
        float sA = s_t[0][e0a] + s_t[0][e0b] + s_t[0][e0c] + s_llr[v0];
        float sB = s_t[0][e1a] + s_t[0][e1b] + s_t[0][e1c] + s_llr[v1];
        out[4 * TOT + b * NV + v0] = sigmoidf(sA);
        out[4 * TOT + b * NV + v1] = sigmoidf(sB);
    }

    // ---- iterations 2..5: VN update (2 weighted extrinsic msgs + llr) then CN ----
    int src = 0;
#pragma unroll
    for (int li = 0; li < 4; li++) {
        const int dst = src ^ 1;
#pragma unroll
        for (int k = 0; k < 6; k++) {
            float2 w = g_w[li][ebase + k];
            float vn = w.x * s_t[src][j1[k]] + w.y * s_t[src][j2[k]] + s_llr[vo[k]];
            u[k] = ftanh_half(vn);
        }
        cn_block(u, tv);
        // dst buffer was last read two barriers ago -> safe without extra barrier
#pragma unroll
        for (int k = 0; k < 6; k++) s_t[dst][ebase + k] = tv[k];
        __syncthreads();

        if (li < 3) {
            float sA = s_t[dst][e0a] + s_t[dst][e0b] + s_t[dst][e0c] + s_llr[v0];
            float sB = s_t[dst][e1a] + s_t[dst][e1b] + s_t[dst][e1c] + s_llr[v1];
            int off = (3 - li) * TOT + b * NV;
            out[off + v0] = sigmoidf(sA);
            out[off + v1] = sigmoidf(sB);
        } else {
            float sA = g_w9[v0][0] * s_t[dst][e0a] + g_w9[v0][1] * s_t[dst][e0b]
                     + g_w9[v0][2] * s_t[dst][e0c] + s_llr[v0];
            float sB = g_w9[v1][0] * s_t[dst][e1a] + g_w9[v1][1] * s_t[dst][e1b]
                     + g_w9[v1][2] * s_t[dst][e1c] + s_llr[v1];
            out[b * NV + v0] = sigmoidf(sA);
            out[b * NV + v1] = sigmoidf(sB);
        }
        src = dst;
    }
}

// ---------------- launch ----------------
extern "C" void kernel_launch(void* const* d_in, const int* in_sizes, int n_in,
                              void* d_out, int out_size) {
    // metadata order: x, M_first, M_cn, M_out, bias_matrix, W1, W3, W5, W7, W9, B0..B4
    const float* x     = (const float*)d_in[0];
    const float* M_out = (const float*)d_in[3];
    const float* W1    = (const float*)d_in[5];
    const float* W3    = (const float*)d_in[6];
    const float* W5    = (const float*)d_in[7];
    const float* W7    = (const float*)d_in[8];
    const float* W9    = (const float*)d_in[9];

    const int scan4 = NV * NE / 4;
    prep1<<<(scan4 + 255) / 256, 256>>>((const float4*)M_out);
    prep2<<<(NE + 255) / 256, 256>>>(W1, W3, W5, W7, W9);
    bp_main<<<BATCH, NCHK>>>(x, (float*)d_out);
}